// round 1
// baseline (speedup 1.0000x reference)
#include <cuda_runtime.h>
#include <math.h>

// Problem constants (fixed by the dataset)
#define BATCH 4
#define LSEQ 4096
#define TSEQ 1024
#define DH 1280
#define DG 768
#define DP 256

// Scratch (allocation-free rule: __device__ globals)
__device__ float g_K[BATCH * LSEQ * DP];   // 16 MB  K = H Wk^T
__device__ float g_Q[BATCH * TSEQ * DP];   //  4 MB  Q = G Wq^T
__device__ float g_S[(size_t)BATCH * TSEQ * LSEQ]; // 64 MB logits -> alpha

// ---------------------------------------------------------------------------
// Generic 128x128 fp32 GEMM, BK=16, 256 threads, 8x8 microtile (split float4).
// BT=true : C = A[M,K] * B[N,K]^T   (both row-major, reduce over contiguous dim)
// BT=false: C = A[M,K] * B[K,N]     (both row-major)
// Grid: (N/128, M/128, batches). Epilogue multiplies by `scale`.
// ---------------------------------------------------------------------------
template <bool BT>
__global__ void __launch_bounds__(256) gemm128(
    const float* __restrict__ A, const float* __restrict__ Bm, float* __restrict__ C,
    int Kdim, int lda, int ldb, int ldc,
    size_t aBatch, size_t bBatch, size_t cBatch, float scale)
{
    A  += (size_t)blockIdx.z * aBatch;
    Bm += (size_t)blockIdx.z * bBatch;
    C  += (size_t)blockIdx.z * cBatch;

    __shared__ float As[16][128];
    __shared__ float Bs[16][128];

    const int tid = threadIdx.x;
    const int tx = tid & 15;        // 0..15 -> columns
    const int ty = tid >> 4;        // 0..15 -> rows
    const int m0 = blockIdx.y * 128;
    const int n0 = blockIdx.x * 128;

    float acc[8][8];
#pragma unroll
    for (int i = 0; i < 8; i++)
#pragma unroll
        for (int j = 0; j < 8; j++) acc[i][j] = 0.0f;

    for (int k0 = 0; k0 < Kdim; k0 += 16) {
        // ---- load A tile: 128 rows x 16 k, transpose into As[k][m]
#pragma unroll
        for (int u = 0; u < 2; u++) {
            int f  = tid * 2 + u;          // 0..511 float4 index
            int r  = f >> 2;               // row 0..127
            int kk = (f & 3) << 2;         // k offset 0,4,8,12
            float4 v = *(const float4*)(A + (size_t)(m0 + r) * lda + k0 + kk);
            As[kk + 0][r] = v.x; As[kk + 1][r] = v.y;
            As[kk + 2][r] = v.z; As[kk + 3][r] = v.w;
        }
        // ---- load B tile
        if (BT) {
#pragma unroll
            for (int u = 0; u < 2; u++) {
                int f  = tid * 2 + u;
                int r  = f >> 2;           // n-row 0..127
                int kk = (f & 3) << 2;
                float4 v = *(const float4*)(Bm + (size_t)(n0 + r) * ldb + k0 + kk);
                Bs[kk + 0][r] = v.x; Bs[kk + 1][r] = v.y;
                Bs[kk + 2][r] = v.z; Bs[kk + 3][r] = v.w;
            }
        } else {
#pragma unroll
            for (int u = 0; u < 2; u++) {
                int f  = tid * 2 + u;
                int kr = f >> 5;           // k row 0..15
                int nc = (f & 31) << 2;    // n col 0..124
                *(float4*)&Bs[kr][nc] =
                    *(const float4*)(Bm + (size_t)(k0 + kr) * ldb + n0 + nc);
            }
        }
        __syncthreads();

#pragma unroll
        for (int k = 0; k < 16; k++) {
            float4 a0 = *(const float4*)&As[k][ty * 4];
            float4 a1 = *(const float4*)&As[k][64 + ty * 4];
            float4 b0 = *(const float4*)&Bs[k][tx * 4];
            float4 b1 = *(const float4*)&Bs[k][64 + tx * 4];
            float ar[8] = {a0.x, a0.y, a0.z, a0.w, a1.x, a1.y, a1.z, a1.w};
            float br[8] = {b0.x, b0.y, b0.z, b0.w, b1.x, b1.y, b1.z, b1.w};
#pragma unroll
            for (int i = 0; i < 8; i++)
#pragma unroll
                for (int j = 0; j < 8; j++)
                    acc[i][j] = fmaf(ar[i], br[j], acc[i][j]);
        }
        __syncthreads();
    }

    // ---- epilogue
#pragma unroll
    for (int i = 0; i < 8; i++) {
        int r = m0 + ((i >> 2) * 64) + ty * 4 + (i & 3);
#pragma unroll
        for (int cj = 0; cj < 2; cj++) {
            float4 v;
            v.x = acc[i][cj * 4 + 0] * scale;
            v.y = acc[i][cj * 4 + 1] * scale;
            v.z = acc[i][cj * 4 + 2] * scale;
            v.w = acc[i][cj * 4 + 3] * scale;
            *(float4*)(C + (size_t)r * ldc + n0 + cj * 64 + tx * 4) = v;
        }
    }
}

// ---------------------------------------------------------------------------
// Masked softmax over the last dim (L=4096), one CTA per (b,t) row, in place.
// mask[b,l] != 0  ->  key removed (prob 0).
// ---------------------------------------------------------------------------
__device__ __forceinline__ float warpMax(float v) {
#pragma unroll
    for (int o = 16; o; o >>= 1) v = fmaxf(v, __shfl_xor_sync(0xffffffffu, v, o));
    return v;
}
__device__ __forceinline__ float warpSum(float v) {
#pragma unroll
    for (int o = 16; o; o >>= 1) v += __shfl_xor_sync(0xffffffffu, v, o);
    return v;
}

__global__ void __launch_bounds__(256) softmax_kernel(float* __restrict__ S,
                                                      const int* __restrict__ mask)
{
    __shared__ float red[8];
    const int row = blockIdx.x;         // 0 .. BATCH*TSEQ-1
    const int b   = row >> 10;          // TSEQ = 1024
    float* s = S + (size_t)row * LSEQ;
    const int* mrow = mask + b * LSEQ;
    const int tid = threadIdx.x;

    float v[16];
    float mx = -1e30f;
#pragma unroll
    for (int i = 0; i < 16; i++) {
        int idx = i * 256 + tid;
        float x = s[idx];
        if (mrow[idx]) x = -1e30f;
        v[i] = x;
        mx = fmaxf(mx, x);
    }
    mx = warpMax(mx);
    if ((tid & 31) == 0) red[tid >> 5] = mx;
    __syncthreads();
    if (tid < 32) {
        float t = (tid < 8) ? red[tid] : -1e30f;
        t = warpMax(t);
        if (tid == 0) red[0] = t;
    }
    __syncthreads();
    mx = red[0];
    __syncthreads();   // protect red[] reuse

    float sum = 0.0f;
#pragma unroll
    for (int i = 0; i < 16; i++) {
        float e = __expf(v[i] - mx);    // masked: exp(~-1e30) == 0
        v[i] = e;
        sum += e;
    }
    sum = warpSum(sum);
    if ((tid & 31) == 0) red[tid >> 5] = sum;
    __syncthreads();
    if (tid < 32) {
        float t = (tid < 8) ? red[tid] : 0.0f;
        t = warpSum(t);
        if (tid == 0) red[0] = t;
    }
    __syncthreads();
    const float inv = 1.0f / red[0];
#pragma unroll
    for (int i = 0; i < 16; i++) s[i * 256 + tid] = v[i] * inv;
}

// ---------------------------------------------------------------------------
extern "C" void kernel_launch(void* const* d_in, const int* in_sizes, int n_in,
                              void* d_out, int out_size)
{
    const float* H    = (const float*)d_in[0]; // [B, L, DH]
    const float* G    = (const float*)d_in[1]; // [B, T, DG]
    const int*   mask = (const int*)  d_in[2]; // [B, L]
    const float* Wk   = (const float*)d_in[3]; // [DP, DH]
    const float* Wq   = (const float*)d_in[4]; // [DP, DG]
    float* Z = (float*)d_out;                  // [B, T, DH]

    float *pK, *pQ, *pS;
    cudaGetSymbolAddress((void**)&pK, g_K);
    cudaGetSymbolAddress((void**)&pQ, g_Q);
    cudaGetSymbolAddress((void**)&pS, g_S);

    dim3 blk(256);

    // 1) K = H * Wk^T    (M = B*L = 16384, N = 256, K = 1280)
    gemm128<true><<<dim3(DP / 128, (BATCH * LSEQ) / 128, 1), blk>>>(
        H, Wk, pK, DH, DH, DH, DP, 0, 0, 0, 1.0f);

    // 2) Q = G * Wq^T    (M = B*T = 4096, N = 256, K = 768)
    gemm128<true><<<dim3(DP / 128, (BATCH * TSEQ) / 128, 1), blk>>>(
        G, Wq, pQ, DG, DG, DG, DP, 0, 0, 0, 1.0f);

    // 3) S = (Q K^T) / sqrt(DP)   per batch (M = T, N = L, K = DP)
    gemm128<true><<<dim3(LSEQ / 128, TSEQ / 128, BATCH), blk>>>(
        pQ, pK, pS, DP, DP, DP, LSEQ,
        (size_t)TSEQ * DP, (size_t)LSEQ * DP, (size_t)TSEQ * LSEQ, 0.0625f);

    // 4) alpha = masked softmax(S) over L, in place
    softmax_kernel<<<BATCH * TSEQ, 256>>>(pS, mask);

    // 5) Z = alpha * H    per batch (M = T, N = DH, K = L)
    gemm128<false><<<dim3(DH / 128, TSEQ / 128, BATCH), blk>>>(
        pS, H, Z, LSEQ, LSEQ, DH, DH,
        (size_t)TSEQ * LSEQ, (size_t)LSEQ * DH, (size_t)TSEQ * DH, 1.0f);
}

// round 4
// speedup vs baseline: 2.1754x; 2.1754x over previous
#include <cuda_runtime.h>
#include <cuda_bf16.h>
#include <cstdint>
#include <math.h>

// Problem constants (fixed by the dataset)
#define BATCH 4
#define LSEQ 4096
#define TSEQ 1024
#define DH 1280
#define DG 768
#define DP 256

// ---------------------------------------------------------------------------
// Scratch (__device__ globals; no allocations allowed)
// ---------------------------------------------------------------------------
__device__ __align__(256) __nv_bfloat16 g_Hhi[BATCH * LSEQ * DH];
__device__ __align__(256) __nv_bfloat16 g_Hlo[BATCH * LSEQ * DH];
__device__ __align__(256) __nv_bfloat16 g_HThi[BATCH * DH * LSEQ];  // [DH, L] per batch
__device__ __align__(256) __nv_bfloat16 g_HTlo[BATCH * DH * LSEQ];
__device__ __align__(256) __nv_bfloat16 g_Ghi[BATCH * TSEQ * DG];
__device__ __align__(256) __nv_bfloat16 g_Glo[BATCH * TSEQ * DG];
__device__ __align__(256) __nv_bfloat16 g_Wkhi[DP * DH];
__device__ __align__(256) __nv_bfloat16 g_Wklo[DP * DH];
__device__ __align__(256) __nv_bfloat16 g_Wqhi[DP * DG];
__device__ __align__(256) __nv_bfloat16 g_Wqlo[DP * DG];
__device__ __align__(256) __nv_bfloat16 g_Khi[BATCH * LSEQ * DP];
__device__ __align__(256) __nv_bfloat16 g_Klo[BATCH * LSEQ * DP];
__device__ __align__(256) __nv_bfloat16 g_Qhi[BATCH * TSEQ * DP];
__device__ __align__(256) __nv_bfloat16 g_Qlo[BATCH * TSEQ * DP];
__device__ __align__(256) float g_S[(size_t)BATCH * TSEQ * LSEQ];   // logits fp32
__device__ __align__(256) __nv_bfloat16 g_Shi[(size_t)BATCH * TSEQ * LSEQ];
__device__ __align__(256) __nv_bfloat16 g_Slo[(size_t)BATCH * TSEQ * LSEQ];

// ---------------------------------------------------------------------------
// PTX helpers (sm_100-base safe: cp.async, ldmatrix, mma.sync only)
// ---------------------------------------------------------------------------
__device__ __forceinline__ uint32_t smem_u32(const void* p) {
    uint32_t a;
    asm("{ .reg .u64 t; cvta.to.shared.u64 t, %1; cvt.u32.u64 %0, t; }" : "=r"(a) : "l"(p));
    return a;
}
#define CP_ASYNC16(dst, src) \
    asm volatile("cp.async.cg.shared.global [%0], [%1], 16;" :: "r"(dst), "l"(src))
#define CP_COMMIT() asm volatile("cp.async.commit_group;" ::: "memory")
#define CP_WAIT0()  asm volatile("cp.async.wait_group 0;" ::: "memory")

__device__ __forceinline__ void ldmatrix_x4(uint32_t& r0, uint32_t& r1, uint32_t& r2,
                                            uint32_t& r3, uint32_t addr) {
    asm volatile("ldmatrix.sync.aligned.m8n8.x4.shared.b16 {%0,%1,%2,%3}, [%4];"
                 : "=r"(r0), "=r"(r1), "=r"(r2), "=r"(r3) : "r"(addr));
}
__device__ __forceinline__ void mma_bf16(float* d, const uint32_t* a, const uint32_t* b) {
    asm volatile("mma.sync.aligned.m16n8k16.row.col.f32.bf16.bf16.f32 "
                 "{%0,%1,%2,%3}, {%4,%5,%6,%7}, {%8,%9}, {%0,%1,%2,%3};"
                 : "+f"(d[0]), "+f"(d[1]), "+f"(d[2]), "+f"(d[3])
                 : "r"(a[0]), "r"(a[1]), "r"(a[2]), "r"(a[3]), "r"(b[0]), "r"(b[1]));
}

// SW128 swizzle on byte offset within a 128x(128B) tile
__device__ __forceinline__ uint32_t sw128(uint32_t bo) { return bo ^ ((bo >> 3) & 0x70); }

// ---------------------------------------------------------------------------
// SMEM layout: 2 stages x (A 16KB + B 16KB) = 64KB; epilogue reuses it.
// ---------------------------------------------------------------------------
#define TILE_BYTES 16384
#define STAGE_BYTES (2 * TILE_BYTES)
#define SMEM_TOTAL (2 * STAGE_BYTES)     // 65536

// Async load of a 128x64 bf16 K-major tile into SW128 SMEM (256 threads).
__device__ __forceinline__ void load_tile_async(uint32_t dst, const __nv_bfloat16* src,
                                                int ldElems) {
    const char* g = (const char*)src;
    const size_t ldb = (size_t)ldElems * 2;
    const int tid = threadIdx.x;
#pragma unroll
    for (int u = 0; u < 4; u++) {
        int i = (u << 8) + tid;          // 0..1023 16B chunks
        int r = i >> 3;                  // row 0..127
        int c = (i & 7) << 4;            // byte col 0..112
        CP_ASYNC16(dst + sw128((uint32_t)((r << 7) + c)), g + (size_t)r * ldb + c);
    }
}

// ---------------------------------------------------------------------------
// mma.sync GEMM: C[M,N] = A[M,K] * B[N,K]^T, bf16 hi/lo 3-pass split.
// EPI=0: fp32 C (scaled). EPI=1: split bf16 (Chi, Clo).
// Grid (N/128, M/128, batches), 256 threads (8 warps, 2M x 4N).
// ---------------------------------------------------------------------------
template <int EPI>
__global__ void __launch_bounds__(256) tc_gemm(
    const __nv_bfloat16* __restrict__ Ahi, const __nv_bfloat16* __restrict__ Alo,
    const __nv_bfloat16* __restrict__ Bhi, const __nv_bfloat16* __restrict__ Blo,
    float* __restrict__ Cf, __nv_bfloat16* __restrict__ Chi, __nv_bfloat16* __restrict__ Clo,
    int Kdim, int lda, int ldb, int ldc,
    size_t aB, size_t bB, size_t cB, float scale)
{
    extern __shared__ char smem[];
    const uint32_t sb = smem_u32(smem);
    const int tid = threadIdx.x;
    const int wid = tid >> 5, lane = tid & 31;
    const int wr = wid & 1, wc = wid >> 1;           // warp tile: rows wr*64, cols wc*32
    const int groupID = lane >> 2, tig = lane & 3;
    const int m0 = blockIdx.y * 128, n0 = blockIdx.x * 128;

    Ahi += (size_t)blockIdx.z * aB;  Alo += (size_t)blockIdx.z * aB;
    Bhi += (size_t)blockIdx.z * bB;  Blo += (size_t)blockIdx.z * bB;

    const __nv_bfloat16* APass[3] = { Ahi, Alo, Ahi };
    const __nv_bfloat16* BPass[3] = { Bhi, Bhi, Blo };
    const int KT = Kdim >> 6;
    const int NT = 3 * KT;

    float acc[4][4][4];
#pragma unroll
    for (int i = 0; i < 4; i++)
#pragma unroll
        for (int j = 0; j < 4; j++)
#pragma unroll
            for (int k = 0; k < 4; k++) acc[i][j][k] = 0.0f;

    // Prologue: stage 0
    load_tile_async(sb, APass[0] + (size_t)m0 * lda, lda);
    load_tile_async(sb + TILE_BYTES, BPass[0] + (size_t)n0 * ldb, ldb);
    CP_COMMIT(); CP_WAIT0();
    __syncthreads();

    // Precomputed ldmatrix lane geometry
    const int aRow = lane & 15;            // + mBase
    const int aColX = (lane >> 4) << 4;    // + kc
    const int bRow = (lane & 7) + ((lane >> 4) & 1) * 8;   // + nBase
    const int bColX = ((lane >> 3) & 1) << 4;              // + kc

    int pass = 0, kt = 0;
#pragma unroll 1
    for (int it = 0; it < NT; ++it) {
        const int cur = it & 1;
        int nkt = kt + 1, npass = pass;
        if (nkt == KT) { nkt = 0; npass++; }
        if (it + 1 < NT) {
            const uint32_t nb = sb + (cur ^ 1) * STAGE_BYTES;
            const int k0 = nkt << 6;
            load_tile_async(nb, APass[npass] + (size_t)m0 * lda + k0, lda);
            load_tile_async(nb + TILE_BYTES, BPass[npass] + (size_t)n0 * ldb + k0, ldb);
            CP_COMMIT();
        }
        const uint32_t aBase = sb + cur * STAGE_BYTES;
        const uint32_t bBase = aBase + TILE_BYTES;
#pragma unroll
        for (int k = 0; k < 4; k++) {
            const int kc = k << 5;       // 16 bf16 = 32 bytes per k16 step
            uint32_t a[4][4];
#pragma unroll
            for (int mi = 0; mi < 4; mi++) {
                int r = wr * 64 + mi * 16 + aRow;
                int c = kc + aColX;
                ldmatrix_x4(a[mi][0], a[mi][1], a[mi][2], a[mi][3],
                            aBase + sw128((uint32_t)((r << 7) + c)));
            }
            uint32_t b[4][2];
#pragma unroll
            for (int p2 = 0; p2 < 2; p2++) {
                int r = wc * 32 + p2 * 16 + bRow;
                int c = kc + bColX;
                ldmatrix_x4(b[p2 * 2][0], b[p2 * 2][1], b[p2 * 2 + 1][0], b[p2 * 2 + 1][1],
                            bBase + sw128((uint32_t)((r << 7) + c)));
            }
#pragma unroll
            for (int mi = 0; mi < 4; mi++)
#pragma unroll
                for (int ni = 0; ni < 4; ni++)
                    mma_bf16(acc[mi][ni], a[mi], b[ni]);
        }
        CP_WAIT0();
        __syncthreads();
        pass = npass; kt = nkt;
    }

    // ---- Epilogue: stage 32-col chunks through SMEM, coalesced global writes
    float* epi = (float*)smem;             // [128][33]
#pragma unroll 1
    for (int ch = 0; ch < 4; ch++) {
        if (wc == ch) {
#pragma unroll
            for (int mi = 0; mi < 4; mi++) {
                int m = wr * 64 + mi * 16 + groupID;
#pragma unroll
                for (int ni = 0; ni < 4; ni++) {
                    int nc = ni * 8 + 2 * tig;
                    epi[m * 33 + nc]           = acc[mi][ni][0] * scale;
                    epi[m * 33 + nc + 1]       = acc[mi][ni][1] * scale;
                    epi[(m + 8) * 33 + nc]     = acc[mi][ni][2] * scale;
                    epi[(m + 8) * 33 + nc + 1] = acc[mi][ni][3] * scale;
                }
            }
        }
        __syncthreads();
#pragma unroll
        for (int u = 0; u < 4; u++) {
            int i = (u << 8) + tid;        // 0..1023 float4 groups
            int r = i >> 3;
            int c4 = (i & 7) << 2;
            float a = epi[r * 33 + c4 + 0];
            float b = epi[r * 33 + c4 + 1];
            float c = epi[r * 33 + c4 + 2];
            float d = epi[r * 33 + c4 + 3];
            size_t off = (size_t)blockIdx.z * cB + (size_t)(m0 + r) * ldc + n0 + ch * 32 + c4;
            if (EPI == 0) {
                *(float4*)(Cf + off) = make_float4(a, b, c, d);
            } else {
                __nv_bfloat16 ha = __float2bfloat16(a), hb = __float2bfloat16(b);
                __nv_bfloat16 hc = __float2bfloat16(c), hd = __float2bfloat16(d);
                __nv_bfloat162* ph = (__nv_bfloat162*)(Chi + off);
                ph[0] = __halves2bfloat162(ha, hb);
                ph[1] = __halves2bfloat162(hc, hd);
                __nv_bfloat162* pl = (__nv_bfloat162*)(Clo + off);
                pl[0] = __halves2bfloat162(__float2bfloat16(a - __bfloat162float(ha)),
                                           __float2bfloat16(b - __bfloat162float(hb)));
                pl[1] = __halves2bfloat162(__float2bfloat16(c - __bfloat162float(hc)),
                                           __float2bfloat16(d - __bfloat162float(hd)));
            }
        }
        __syncthreads();
    }
}

// ---------------------------------------------------------------------------
// fp32 -> bf16 hi/lo split (flat)
// ---------------------------------------------------------------------------
__global__ void __launch_bounds__(256) split_kernel(
    const float4* __restrict__ x, __nv_bfloat162* __restrict__ hi,
    __nv_bfloat162* __restrict__ lo, int n4)
{
    int i = blockIdx.x * 256 + threadIdx.x;
    if (i >= n4) return;
    float4 v = x[i];
    __nv_bfloat16 ha = __float2bfloat16(v.x), hb = __float2bfloat16(v.y);
    __nv_bfloat16 hc = __float2bfloat16(v.z), hd = __float2bfloat16(v.w);
    hi[i * 2 + 0] = __halves2bfloat162(ha, hb);
    hi[i * 2 + 1] = __halves2bfloat162(hc, hd);
    lo[i * 2 + 0] = __halves2bfloat162(__float2bfloat16(v.x - __bfloat162float(ha)),
                                       __float2bfloat16(v.y - __bfloat162float(hb)));
    lo[i * 2 + 1] = __halves2bfloat162(__float2bfloat16(v.z - __bfloat162float(hc)),
                                       __float2bfloat16(v.w - __bfloat162float(hd)));
}

// ---------------------------------------------------------------------------
// H [B, L, DH] fp32 -> HT [B, DH, L] bf16 hi/lo (tiled transpose)
// ---------------------------------------------------------------------------
__global__ void __launch_bounds__(256) transpose_split_kernel(
    const float* __restrict__ X, __nv_bfloat16* __restrict__ hi, __nv_bfloat16* __restrict__ lo)
{
    __shared__ float t[32][33];
    const int b = blockIdx.z;
    const int d0 = blockIdx.x << 5, l0 = blockIdx.y << 5;
    const int tx = threadIdx.x & 31, ty = threadIdx.x >> 5;
    const float* Xb = X + (size_t)b * LSEQ * DH;
#pragma unroll
    for (int k = 0; k < 4; k++)
        t[ty + 8 * k][tx] = Xb[(size_t)(l0 + ty + 8 * k) * DH + d0 + tx];
    __syncthreads();
    const size_t obase = (size_t)b * DH * LSEQ;
#pragma unroll
    for (int k = 0; k < 4; k++) {
        int d = d0 + ty + 8 * k;
        float v = t[tx][ty + 8 * k];
        __nv_bfloat16 h = __float2bfloat16(v);
        hi[obase + (size_t)d * LSEQ + l0 + tx] = h;
        lo[obase + (size_t)d * LSEQ + l0 + tx] = __float2bfloat16(v - __bfloat162float(h));
    }
}

// ---------------------------------------------------------------------------
// Masked softmax over L=4096; fp32 logits -> split bf16 alpha.
// ---------------------------------------------------------------------------
__device__ __forceinline__ float warpMax(float v) {
#pragma unroll
    for (int o = 16; o; o >>= 1) v = fmaxf(v, __shfl_xor_sync(0xffffffffu, v, o));
    return v;
}
__device__ __forceinline__ float warpSum(float v) {
#pragma unroll
    for (int o = 16; o; o >>= 1) v += __shfl_xor_sync(0xffffffffu, v, o);
    return v;
}

__global__ void __launch_bounds__(256) softmax_kernel(
    const float* __restrict__ S, const int* __restrict__ mask,
    __nv_bfloat16* __restrict__ Ahi, __nv_bfloat16* __restrict__ Alo)
{
    __shared__ float red[8];
    const int row = blockIdx.x;
    const int b = row >> 10;                 // TSEQ = 1024
    const float* s = S + (size_t)row * LSEQ;
    const int* mrow = mask + b * LSEQ;
    const int tid = threadIdx.x;

    float v[16];
    float mx = -1e30f;
#pragma unroll
    for (int i = 0; i < 16; i++) {
        int idx = i * 256 + tid;
        float x = s[idx];
        if (mrow[idx]) x = -1e30f;
        v[i] = x;
        mx = fmaxf(mx, x);
    }
    mx = warpMax(mx);
    if ((tid & 31) == 0) red[tid >> 5] = mx;
    __syncthreads();
    if (tid < 32) {
        float t = (tid < 8) ? red[tid] : -1e30f;
        t = warpMax(t);
        if (tid == 0) red[0] = t;
    }
    __syncthreads();
    mx = red[0];
    __syncthreads();

    float sum = 0.0f;
#pragma unroll
    for (int i = 0; i < 16; i++) {
        float e = __expf(v[i] - mx);
        v[i] = e;
        sum += e;
    }
    sum = warpSum(sum);
    if ((tid & 31) == 0) red[tid >> 5] = sum;
    __syncthreads();
    if (tid < 32) {
        float t = (tid < 8) ? red[tid] : 0.0f;
        t = warpSum(t);
        if (tid == 0) red[0] = t;
    }
    __syncthreads();
    const float inv = 1.0f / red[0];
    __nv_bfloat16* ahr = Ahi + (size_t)row * LSEQ;
    __nv_bfloat16* alr = Alo + (size_t)row * LSEQ;
#pragma unroll
    for (int i = 0; i < 16; i++) {
        int idx = i * 256 + tid;
        float a = v[i] * inv;
        __nv_bfloat16 h = __float2bfloat16(a);
        ahr[idx] = h;
        alr[idx] = __float2bfloat16(a - __bfloat162float(h));
    }
}

// ---------------------------------------------------------------------------
extern "C" void kernel_launch(void* const* d_in, const int* in_sizes, int n_in,
                              void* d_out, int out_size)
{
    const float* H    = (const float*)d_in[0]; // [B, L, DH]
    const float* G    = (const float*)d_in[1]; // [B, T, DG]
    const int*   mask = (const int*)  d_in[2]; // [B, L]
    const float* Wk   = (const float*)d_in[3]; // [DP, DH]
    const float* Wq   = (const float*)d_in[4]; // [DP, DG]
    float* Z = (float*)d_out;                  // [B, T, DH]

    __nv_bfloat16 *pHhi, *pHlo, *pHThi, *pHTlo, *pGhi, *pGlo;
    __nv_bfloat16 *pWkhi, *pWklo, *pWqhi, *pWqlo;
    __nv_bfloat16 *pKhi, *pKlo, *pQhi, *pQlo, *pShi, *pSlo;
    float* pS;
    cudaGetSymbolAddress((void**)&pHhi, g_Hhi);   cudaGetSymbolAddress((void**)&pHlo, g_Hlo);
    cudaGetSymbolAddress((void**)&pHThi, g_HThi); cudaGetSymbolAddress((void**)&pHTlo, g_HTlo);
    cudaGetSymbolAddress((void**)&pGhi, g_Ghi);   cudaGetSymbolAddress((void**)&pGlo, g_Glo);
    cudaGetSymbolAddress((void**)&pWkhi, g_Wkhi); cudaGetSymbolAddress((void**)&pWklo, g_Wklo);
    cudaGetSymbolAddress((void**)&pWqhi, g_Wqhi); cudaGetSymbolAddress((void**)&pWqlo, g_Wqlo);
    cudaGetSymbolAddress((void**)&pKhi, g_Khi);   cudaGetSymbolAddress((void**)&pKlo, g_Klo);
    cudaGetSymbolAddress((void**)&pQhi, g_Qhi);   cudaGetSymbolAddress((void**)&pQlo, g_Qlo);
    cudaGetSymbolAddress((void**)&pShi, g_Shi);   cudaGetSymbolAddress((void**)&pSlo, g_Slo);
    cudaGetSymbolAddress((void**)&pS, g_S);

    cudaFuncSetAttribute(tc_gemm<0>, cudaFuncAttributeMaxDynamicSharedMemorySize, SMEM_TOTAL);
    cudaFuncSetAttribute(tc_gemm<1>, cudaFuncAttributeMaxDynamicSharedMemorySize, SMEM_TOTAL);

    // ---- conversions
    {
        int n4;
        n4 = (BATCH * LSEQ * DH) / 4;
        split_kernel<<<(n4 + 255) / 256, 256>>>((const float4*)H, (__nv_bfloat162*)pHhi,
                                                (__nv_bfloat162*)pHlo, n4);
        n4 = (BATCH * TSEQ * DG) / 4;
        split_kernel<<<(n4 + 255) / 256, 256>>>((const float4*)G, (__nv_bfloat162*)pGhi,
                                                (__nv_bfloat162*)pGlo, n4);
        n4 = (DP * DH) / 4;
        split_kernel<<<(n4 + 255) / 256, 256>>>((const float4*)Wk, (__nv_bfloat162*)pWkhi,
                                                (__nv_bfloat162*)pWklo, n4);
        n4 = (DP * DG) / 4;
        split_kernel<<<(n4 + 255) / 256, 256>>>((const float4*)Wq, (__nv_bfloat162*)pWqhi,
                                                (__nv_bfloat162*)pWqlo, n4);
        transpose_split_kernel<<<dim3(DH / 32, LSEQ / 32, BATCH), 256>>>(H, pHThi, pHTlo);
    }

    // 1) K = H * Wk^T  -> split bf16   (M = B*L, N = DP, K = DH)
    tc_gemm<1><<<dim3(DP / 128, (BATCH * LSEQ) / 128, 1), 256, SMEM_TOTAL>>>(
        pHhi, pHlo, pWkhi, pWklo, nullptr, pKhi, pKlo,
        DH, DH, DH, DP, 0, 0, 0, 1.0f);

    // 2) Q = G * Wq^T  -> split bf16   (M = B*T, N = DP, K = DG)
    tc_gemm<1><<<dim3(DP / 128, (BATCH * TSEQ) / 128, 1), 256, SMEM_TOTAL>>>(
        pGhi, pGlo, pWqhi, pWqlo, nullptr, pQhi, pQlo,
        DG, DG, DG, DP, 0, 0, 0, 1.0f);

    // 3) S = (Q K^T) / 16  -> fp32     (per batch: M = T, N = L, K = DP)
    tc_gemm<0><<<dim3(LSEQ / 128, TSEQ / 128, BATCH), 256, SMEM_TOTAL>>>(
        pQhi, pQlo, pKhi, pKlo, pS, nullptr, nullptr,
        DP, DP, DP, LSEQ,
        (size_t)TSEQ * DP, (size_t)LSEQ * DP, (size_t)TSEQ * LSEQ, 0.0625f);

    // 4) alpha = masked softmax(S) -> split bf16
    softmax_kernel<<<BATCH * TSEQ, 256>>>(pS, mask, pShi, pSlo);

    // 5) Z = alpha * H  (per batch: M = T, N = DH, K = L; B operand = H^T)
    tc_gemm<0><<<dim3(DH / 128, TSEQ / 128, BATCH), 256, SMEM_TOTAL>>>(
        pShi, pSlo, pHThi, pHTlo, Z, nullptr, nullptr,
        LSEQ, LSEQ, LSEQ, DH,
        (size_t)TSEQ * LSEQ, (size_t)DH * LSEQ, (size_t)TSEQ * DH, 1.0f);
}

// round 5
// speedup vs baseline: 4.6586x; 2.1415x over previous
#include <cuda_runtime.h>
#include <cuda_bf16.h>
#include <cstdint>
#include <math.h>

// Problem constants (fixed by the dataset)
#define BATCH 4
#define LSEQ 4096
#define TSEQ 1024
#define DH 1280
#define DG 768
#define DP 256

// ---------------------------------------------------------------------------
// Scratch (__device__ globals; no allocations allowed)
// ---------------------------------------------------------------------------
__device__ __align__(256) __nv_bfloat16 g_Hhi[BATCH * LSEQ * DH];   // compacted Hc
__device__ __align__(256) __nv_bfloat16 g_Hlo[BATCH * LSEQ * DH];
__device__ __align__(256) __nv_bfloat16 g_HThi[BATCH * DH * LSEQ];  // compacted Hc^T
__device__ __align__(256) __nv_bfloat16 g_HTlo[BATCH * DH * LSEQ];
__device__ __align__(256) __nv_bfloat16 g_Ghi[BATCH * TSEQ * DG];
__device__ __align__(256) __nv_bfloat16 g_Glo[BATCH * TSEQ * DG];
__device__ __align__(256) __nv_bfloat16 g_Wkhi[DP * DH];
__device__ __align__(256) __nv_bfloat16 g_Wklo[DP * DH];
__device__ __align__(256) __nv_bfloat16 g_Wqhi[DP * DG];
__device__ __align__(256) __nv_bfloat16 g_Wqlo[DP * DG];
__device__ __align__(256) __nv_bfloat16 g_Khi[BATCH * LSEQ * DP];
__device__ __align__(256) __nv_bfloat16 g_Klo[BATCH * LSEQ * DP];
__device__ __align__(256) __nv_bfloat16 g_Qhi[BATCH * TSEQ * DP];
__device__ __align__(256) __nv_bfloat16 g_Qlo[BATCH * TSEQ * DP];
__device__ __align__(256) float g_S[(size_t)BATCH * TSEQ * LSEQ];
__device__ __align__(256) __nv_bfloat16 g_Shi[(size_t)BATCH * TSEQ * LSEQ];
__device__ __align__(256) __nv_bfloat16 g_Slo[(size_t)BATCH * TSEQ * LSEQ];
__device__ int g_idx[BATCH * LSEQ];    // compaction gather indices
__device__ int g_Lc[BATCH];            // unmasked count per batch
__device__ int g_LcPad[BATCH];         // Lc rounded up to 128

// ---------------------------------------------------------------------------
// PTX helpers (sm_100-base safe: cp.async, ldmatrix, mma.sync only)
// ---------------------------------------------------------------------------
__device__ __forceinline__ uint32_t smem_u32(const void* p) {
    uint32_t a;
    asm("{ .reg .u64 t; cvta.to.shared.u64 t, %1; cvt.u32.u64 %0, t; }" : "=r"(a) : "l"(p));
    return a;
}
#define CP_ASYNC16(dst, src) \
    asm volatile("cp.async.cg.shared.global [%0], [%1], 16;" :: "r"(dst), "l"(src))
#define CP_COMMIT() asm volatile("cp.async.commit_group;" ::: "memory")
#define CP_WAIT0()  asm volatile("cp.async.wait_group 0;" ::: "memory")

__device__ __forceinline__ void ldmatrix_x4(uint32_t& r0, uint32_t& r1, uint32_t& r2,
                                            uint32_t& r3, uint32_t addr) {
    asm volatile("ldmatrix.sync.aligned.m8n8.x4.shared.b16 {%0,%1,%2,%3}, [%4];"
                 : "=r"(r0), "=r"(r1), "=r"(r2), "=r"(r3) : "r"(addr));
}
__device__ __forceinline__ void mma_bf16(float* d, const uint32_t* a, const uint32_t* b) {
    asm volatile("mma.sync.aligned.m16n8k16.row.col.f32.bf16.bf16.f32 "
                 "{%0,%1,%2,%3}, {%4,%5,%6,%7}, {%8,%9}, {%0,%1,%2,%3};"
                 : "+f"(d[0]), "+f"(d[1]), "+f"(d[2]), "+f"(d[3])
                 : "r"(a[0]), "r"(a[1]), "r"(a[2]), "r"(a[3]), "r"(b[0]), "r"(b[1]));
}
__device__ __forceinline__ uint32_t sw128(uint32_t bo) { return bo ^ ((bo >> 3) & 0x70); }

// ---------------------------------------------------------------------------
// SMEM: 2 stages x 4 tiles (Ahi, Alo, Bhi, Blo) x 16KB = 128KB
// ---------------------------------------------------------------------------
#define TILE_BYTES 16384
#define STAGE_BYTES (4 * TILE_BYTES)
#define SMEM_TOTAL (2 * STAGE_BYTES)    // 131072

__device__ __forceinline__ void load_tile_async(uint32_t dst, const __nv_bfloat16* src,
                                                int ldElems) {
    const char* g = (const char*)src;
    const size_t ldb = (size_t)ldElems * 2;
    const int tid = threadIdx.x;
#pragma unroll
    for (int u = 0; u < 4; u++) {
        int i = (u << 8) + tid;          // 0..1023 16B chunks
        int r = i >> 3;                  // row 0..127
        int c = (i & 7) << 4;            // byte col 0..112
        CP_ASYNC16(dst + sw128((uint32_t)((r << 7) + c)), g + (size_t)r * ldb + c);
    }
}

// ---------------------------------------------------------------------------
// Fused-pass mma.sync GEMM: C[M,N] = A[M,K]*B[N,K]^T with hi/lo 3-product split
// per K-tile (loads Ahi/Alo/Bhi/Blo once, issues hh + lh + hl products).
// EPI=0: fp32 C.  EPI=1: split bf16 C.
// EXIT=0 none; EXIT=1 exit if m0>=dynK[z]; EXIT=2 exit if n0>=dynK[z].
// KdimStatic=0 -> Kdim = dynK[z].
// ---------------------------------------------------------------------------
template <int EPI, int EXIT>
__global__ void __launch_bounds__(256) tc_gemm(
    const __nv_bfloat16* __restrict__ Ahi, const __nv_bfloat16* __restrict__ Alo,
    const __nv_bfloat16* __restrict__ Bhi, const __nv_bfloat16* __restrict__ Blo,
    float* __restrict__ Cf, __nv_bfloat16* __restrict__ Chi, __nv_bfloat16* __restrict__ Clo,
    int KdimStatic, const int* __restrict__ dynK,
    int lda, int ldb, int ldc, size_t aB, size_t bB, size_t cB, float scale)
{
    extern __shared__ char smem[];
    const uint32_t sb = smem_u32(smem);
    const int tid = threadIdx.x;
    const int wid = tid >> 5, lane = tid & 31;
    const int wr = wid & 1, wc = wid >> 1;
    const int groupID = lane >> 2, tig = lane & 3;
    const int m0 = blockIdx.y * 128, n0 = blockIdx.x * 128;

    const int lim = dynK ? dynK[blockIdx.z] : 0;
    if (EXIT == 1 && m0 >= lim) return;
    if (EXIT == 2 && n0 >= lim) return;
    const int Kdim = KdimStatic ? KdimStatic : lim;
    const int KT = Kdim >> 6;

    Ahi += (size_t)blockIdx.z * aB;  Alo += (size_t)blockIdx.z * aB;
    Bhi += (size_t)blockIdx.z * bB;  Blo += (size_t)blockIdx.z * bB;

    float acc[4][4][4];
#pragma unroll
    for (int i = 0; i < 4; i++)
#pragma unroll
        for (int j = 0; j < 4; j++)
#pragma unroll
            for (int k = 0; k < 4; k++) acc[i][j][k] = 0.0f;

    // ldmatrix lane geometry
    const int aRow = lane & 15;
    const int aColX = (lane >> 4) << 4;
    const int bRow = (lane & 7) + ((lane >> 4) & 1) * 8;
    const int bColX = ((lane >> 3) & 1) << 4;

    if (KT > 0) {
        // Prologue: stage 0
        load_tile_async(sb,                 Ahi + (size_t)m0 * lda, lda);
        load_tile_async(sb + TILE_BYTES,    Alo + (size_t)m0 * lda, lda);
        load_tile_async(sb + 2*TILE_BYTES,  Bhi + (size_t)n0 * ldb, ldb);
        load_tile_async(sb + 3*TILE_BYTES,  Blo + (size_t)n0 * ldb, ldb);
        CP_COMMIT(); CP_WAIT0();
        __syncthreads();

#pragma unroll 1
        for (int it = 0; it < KT; ++it) {
            const int cur = it & 1;
            if (it + 1 < KT) {
                const uint32_t nb = sb + (cur ^ 1) * STAGE_BYTES;
                const int k0 = (it + 1) << 6;
                load_tile_async(nb,                Ahi + (size_t)m0 * lda + k0, lda);
                load_tile_async(nb + TILE_BYTES,   Alo + (size_t)m0 * lda + k0, lda);
                load_tile_async(nb + 2*TILE_BYTES, Bhi + (size_t)n0 * ldb + k0, ldb);
                load_tile_async(nb + 3*TILE_BYTES, Blo + (size_t)n0 * ldb + k0, ldb);
                CP_COMMIT();
            }
            const uint32_t base = sb + cur * STAGE_BYTES;
#pragma unroll
            for (int k = 0; k < 4; k++) {
                const int kc = k << 5;
                uint32_t ahf[4][4], alf[4][4];
#pragma unroll
                for (int mi = 0; mi < 4; mi++) {
                    int r = wr * 64 + mi * 16 + aRow;
                    uint32_t off = sw128((uint32_t)((r << 7) + kc + aColX));
                    ldmatrix_x4(ahf[mi][0], ahf[mi][1], ahf[mi][2], ahf[mi][3], base + off);
                    ldmatrix_x4(alf[mi][0], alf[mi][1], alf[mi][2], alf[mi][3],
                                base + TILE_BYTES + off);
                }
                uint32_t bhf[4][2], blf[4][2];
#pragma unroll
                for (int p2 = 0; p2 < 2; p2++) {
                    int r = wc * 32 + p2 * 16 + bRow;
                    uint32_t off = sw128((uint32_t)((r << 7) + kc + bColX));
                    ldmatrix_x4(bhf[p2*2][0], bhf[p2*2][1], bhf[p2*2+1][0], bhf[p2*2+1][1],
                                base + 2*TILE_BYTES + off);
                    ldmatrix_x4(blf[p2*2][0], blf[p2*2][1], blf[p2*2+1][0], blf[p2*2+1][1],
                                base + 3*TILE_BYTES + off);
                }
#pragma unroll
                for (int mi = 0; mi < 4; mi++)
#pragma unroll
                    for (int ni = 0; ni < 4; ni++) {
                        mma_bf16(acc[mi][ni], ahf[mi], bhf[ni]);
                        mma_bf16(acc[mi][ni], alf[mi], bhf[ni]);
                        mma_bf16(acc[mi][ni], ahf[mi], blf[ni]);
                    }
            }
            CP_WAIT0();
            __syncthreads();
        }
    }

    // ---- Epilogue: 32-col chunks through SMEM, coalesced global writes
    float* epi = (float*)smem;             // [128][33]
#pragma unroll 1
    for (int ch = 0; ch < 4; ch++) {
        if (wc == ch) {
#pragma unroll
            for (int mi = 0; mi < 4; mi++) {
                int m = wr * 64 + mi * 16 + groupID;
#pragma unroll
                for (int ni = 0; ni < 4; ni++) {
                    int nc = ni * 8 + 2 * tig;
                    epi[m * 33 + nc]           = acc[mi][ni][0] * scale;
                    epi[m * 33 + nc + 1]       = acc[mi][ni][1] * scale;
                    epi[(m + 8) * 33 + nc]     = acc[mi][ni][2] * scale;
                    epi[(m + 8) * 33 + nc + 1] = acc[mi][ni][3] * scale;
                }
            }
        }
        __syncthreads();
#pragma unroll
        for (int u = 0; u < 4; u++) {
            int i = (u << 8) + tid;
            int r = i >> 3;
            int c4 = (i & 7) << 2;
            float a = epi[r * 33 + c4 + 0];
            float b = epi[r * 33 + c4 + 1];
            float c = epi[r * 33 + c4 + 2];
            float d = epi[r * 33 + c4 + 3];
            size_t off = (size_t)blockIdx.z * cB + (size_t)(m0 + r) * ldc + n0 + ch * 32 + c4;
            if (EPI == 0) {
                *(float4*)(Cf + off) = make_float4(a, b, c, d);
            } else {
                __nv_bfloat16 ha = __float2bfloat16(a), hb = __float2bfloat16(b);
                __nv_bfloat16 hc = __float2bfloat16(c), hd = __float2bfloat16(d);
                __nv_bfloat162* ph = (__nv_bfloat162*)(Chi + off);
                ph[0] = __halves2bfloat162(ha, hb);
                ph[1] = __halves2bfloat162(hc, hd);
                __nv_bfloat162* pl = (__nv_bfloat162*)(Clo + off);
                pl[0] = __halves2bfloat162(__float2bfloat16(a - __bfloat162float(ha)),
                                           __float2bfloat16(b - __bfloat162float(hb)));
                pl[1] = __halves2bfloat162(__float2bfloat16(c - __bfloat162float(hc)),
                                           __float2bfloat16(d - __bfloat162float(hd)));
            }
        }
        __syncthreads();
    }
}

// ---------------------------------------------------------------------------
// Mask scan: per batch, gather indices of unmasked keys + counts.
// ---------------------------------------------------------------------------
__global__ void __launch_bounds__(256) mask_scan_kernel(const int* __restrict__ mask) {
    __shared__ int wsum[8], woff[8];
    const int b = blockIdx.x;
    const int* m = mask + b * LSEQ;
    const int tid = threadIdx.x, lane = tid & 31, wid = tid >> 5;
    const int base_l = tid * 16;
    int keep = 0, cnt = 0;
#pragma unroll
    for (int i = 0; i < 16; i++) {
        int k = (m[base_l + i] == 0);
        keep |= k << i;
        cnt += k;
    }
    int incl = cnt;
#pragma unroll
    for (int o = 1; o < 32; o <<= 1) {
        int v = __shfl_up_sync(0xffffffffu, incl, o);
        if (lane >= o) incl += v;
    }
    if (lane == 31) wsum[wid] = incl;
    __syncthreads();
    if (tid == 0) {
        int acc = 0;
#pragma unroll
        for (int w = 0; w < 8; w++) { woff[w] = acc; acc += wsum[w]; }
        g_Lc[b] = acc;
        g_LcPad[b] = (acc + 127) & ~127;
    }
    __syncthreads();
    int pos = woff[wid] + incl - cnt;
    int* idx = g_idx + b * LSEQ;
#pragma unroll
    for (int i = 0; i < 16; i++) {
        if ((keep >> i) & 1) idx[pos++] = base_l + i;
    }
}

// ---------------------------------------------------------------------------
// Gather + split H rows into compacted Hc (bf16 hi/lo); zero pad rows.
// Grid: (LSEQ, BATCH), 256 threads.
// ---------------------------------------------------------------------------
__global__ void __launch_bounds__(256) gather_split_H(const float* __restrict__ H) {
    const int b = blockIdx.y, j = blockIdx.x;
    const int lcp = g_LcPad[b];
    if (j >= lcp) return;
    const int lc = g_Lc[b];
    uint32_t* hi = (uint32_t*)(g_Hhi + ((size_t)b * LSEQ + j) * DH);
    uint32_t* lo = (uint32_t*)(g_Hlo + ((size_t)b * LSEQ + j) * DH);
    if (j < lc) {
        const float4* src = (const float4*)(H + ((size_t)b * LSEQ + g_idx[b * LSEQ + j]) * DH);
        for (int i = threadIdx.x; i < DH / 4; i += 256) {
            float4 v = src[i];
            __nv_bfloat16 ha = __float2bfloat16(v.x), hb = __float2bfloat16(v.y);
            __nv_bfloat16 hc = __float2bfloat16(v.z), hd = __float2bfloat16(v.w);
            ((__nv_bfloat162*)hi)[i * 2 + 0] = __halves2bfloat162(ha, hb);
            ((__nv_bfloat162*)hi)[i * 2 + 1] = __halves2bfloat162(hc, hd);
            ((__nv_bfloat162*)lo)[i * 2 + 0] =
                __halves2bfloat162(__float2bfloat16(v.x - __bfloat162float(ha)),
                                   __float2bfloat16(v.y - __bfloat162float(hb)));
            ((__nv_bfloat162*)lo)[i * 2 + 1] =
                __halves2bfloat162(__float2bfloat16(v.z - __bfloat162float(hc)),
                                   __float2bfloat16(v.w - __bfloat162float(hd)));
        }
    } else {
        for (int i = threadIdx.x; i < DH / 2; i += 256) { hi[i] = 0u; lo[i] = 0u; }
    }
}

// ---------------------------------------------------------------------------
// Gather + transpose + split: HcT[b][d][j] (zero for j >= Lc).
// Grid: (DH/32, LSEQ/32, BATCH), 256 threads.
// ---------------------------------------------------------------------------
__global__ void __launch_bounds__(256) gather_transpose_split(const float* __restrict__ X) {
    __shared__ float t[32][33];
    const int b = blockIdx.z;
    const int l0 = blockIdx.y << 5;
    if (l0 >= g_LcPad[b]) return;
    const int lc = g_Lc[b];
    const int d0 = blockIdx.x << 5;
    const int tx = threadIdx.x & 31, ty = threadIdx.x >> 5;
    const float* Xb = X + (size_t)b * LSEQ * DH;
    const int* idx = g_idx + b * LSEQ;
#pragma unroll
    for (int k = 0; k < 4; k++) {
        int l = l0 + ty + 8 * k;
        t[ty + 8 * k][tx] = (l < lc) ? Xb[(size_t)idx[l] * DH + d0 + tx] : 0.0f;
    }
    __syncthreads();
    const size_t obase = (size_t)b * DH * LSEQ;
#pragma unroll
    for (int k = 0; k < 4; k++) {
        int d = d0 + ty + 8 * k;
        float v = t[tx][ty + 8 * k];
        __nv_bfloat16 h = __float2bfloat16(v);
        g_HThi[obase + (size_t)d * LSEQ + l0 + tx] = h;
        g_HTlo[obase + (size_t)d * LSEQ + l0 + tx] = __float2bfloat16(v - __bfloat162float(h));
    }
}

// ---------------------------------------------------------------------------
// fp32 -> bf16 hi/lo split (flat)
// ---------------------------------------------------------------------------
__global__ void __launch_bounds__(256) split_kernel(
    const float4* __restrict__ x, __nv_bfloat162* __restrict__ hi,
    __nv_bfloat162* __restrict__ lo, int n4)
{
    int i = blockIdx.x * 256 + threadIdx.x;
    if (i >= n4) return;
    float4 v = x[i];
    __nv_bfloat16 ha = __float2bfloat16(v.x), hb = __float2bfloat16(v.y);
    __nv_bfloat16 hc = __float2bfloat16(v.z), hd = __float2bfloat16(v.w);
    hi[i * 2 + 0] = __halves2bfloat162(ha, hb);
    hi[i * 2 + 1] = __halves2bfloat162(hc, hd);
    lo[i * 2 + 0] = __halves2bfloat162(__float2bfloat16(v.x - __bfloat162float(ha)),
                                       __float2bfloat16(v.y - __bfloat162float(hb)));
    lo[i * 2 + 1] = __halves2bfloat162(__float2bfloat16(v.z - __bfloat162float(hc)),
                                       __float2bfloat16(v.w - __bfloat162float(hd)));
}

// ---------------------------------------------------------------------------
// Softmax over compacted row (length Lc); writes split bf16 alpha, zero pad.
// ---------------------------------------------------------------------------
__device__ __forceinline__ float warpMax(float v) {
#pragma unroll
    for (int o = 16; o; o >>= 1) v = fmaxf(v, __shfl_xor_sync(0xffffffffu, v, o));
    return v;
}
__device__ __forceinline__ float warpSum(float v) {
#pragma unroll
    for (int o = 16; o; o >>= 1) v += __shfl_xor_sync(0xffffffffu, v, o);
    return v;
}

__global__ void __launch_bounds__(256) softmax_kernel(
    const float* __restrict__ S, __nv_bfloat16* __restrict__ Ahi,
    __nv_bfloat16* __restrict__ Alo)
{
    __shared__ float red[8];
    const int row = blockIdx.x;
    const int b = row >> 10;                 // TSEQ = 1024
    const int lc = g_Lc[b], lcp = g_LcPad[b];
    const float* s = S + (size_t)row * LSEQ;
    const int tid = threadIdx.x;

    float v[16];
    float mx = -1e30f;
#pragma unroll
    for (int i = 0; i < 16; i++) {
        int idx = i * 256 + tid;
        float x = (idx < lc) ? s[idx] : -1e30f;
        v[i] = x;
        mx = fmaxf(mx, x);
    }
    mx = warpMax(mx);
    if ((tid & 31) == 0) red[tid >> 5] = mx;
    __syncthreads();
    if (tid < 32) {
        float t = (tid < 8) ? red[tid] : -1e30f;
        t = warpMax(t);
        if (tid == 0) red[0] = t;
    }
    __syncthreads();
    mx = red[0];
    __syncthreads();

    float sum = 0.0f;
#pragma unroll
    for (int i = 0; i < 16; i++) {
        float e = __expf(v[i] - mx);
        v[i] = e;
        sum += e;
    }
    sum = warpSum(sum);
    if ((tid & 31) == 0) red[tid >> 5] = sum;
    __syncthreads();
    if (tid < 32) {
        float t = (tid < 8) ? red[tid] : 0.0f;
        t = warpSum(t);
        if (tid == 0) red[0] = t;
    }
    __syncthreads();
    const float inv = 1.0f / red[0];
    __nv_bfloat16* ahr = Ahi + (size_t)row * LSEQ;
    __nv_bfloat16* alr = Alo + (size_t)row * LSEQ;
#pragma unroll
    for (int i = 0; i < 16; i++) {
        int idx = i * 256 + tid;
        if (idx < lc) {
            float a = v[i] * inv;
            __nv_bfloat16 h = __float2bfloat16(a);
            ahr[idx] = h;
            alr[idx] = __float2bfloat16(a - __bfloat162float(h));
        } else if (idx < lcp) {
            ahr[idx] = __float2bfloat16(0.0f);
            alr[idx] = __float2bfloat16(0.0f);
        }
    }
}

// ---------------------------------------------------------------------------
extern "C" void kernel_launch(void* const* d_in, const int* in_sizes, int n_in,
                              void* d_out, int out_size)
{
    const float* H    = (const float*)d_in[0]; // [B, L, DH]
    const float* G    = (const float*)d_in[1]; // [B, T, DG]
    const int*   mask = (const int*)  d_in[2]; // [B, L]
    const float* Wk   = (const float*)d_in[3]; // [DP, DH]
    const float* Wq   = (const float*)d_in[4]; // [DP, DG]
    float* Z = (float*)d_out;                  // [B, T, DH]

    __nv_bfloat16 *pHhi, *pHlo, *pHThi, *pHTlo, *pGhi, *pGlo;
    __nv_bfloat16 *pWkhi, *pWklo, *pWqhi, *pWqlo;
    __nv_bfloat16 *pKhi, *pKlo, *pQhi, *pQlo, *pShi, *pSlo;
    float* pS;
    int *pLcPad;
    cudaGetSymbolAddress((void**)&pHhi, g_Hhi);   cudaGetSymbolAddress((void**)&pHlo, g_Hlo);
    cudaGetSymbolAddress((void**)&pHThi, g_HThi); cudaGetSymbolAddress((void**)&pHTlo, g_HTlo);
    cudaGetSymbolAddress((void**)&pGhi, g_Ghi);   cudaGetSymbolAddress((void**)&pGlo, g_Glo);
    cudaGetSymbolAddress((void**)&pWkhi, g_Wkhi); cudaGetSymbolAddress((void**)&pWklo, g_Wklo);
    cudaGetSymbolAddress((void**)&pWqhi, g_Wqhi); cudaGetSymbolAddress((void**)&pWqlo, g_Wqlo);
    cudaGetSymbolAddress((void**)&pKhi, g_Khi);   cudaGetSymbolAddress((void**)&pKlo, g_Klo);
    cudaGetSymbolAddress((void**)&pQhi, g_Qhi);   cudaGetSymbolAddress((void**)&pQlo, g_Qlo);
    cudaGetSymbolAddress((void**)&pShi, g_Shi);   cudaGetSymbolAddress((void**)&pSlo, g_Slo);
    cudaGetSymbolAddress((void**)&pS, g_S);
    cudaGetSymbolAddress((void**)&pLcPad, g_LcPad);

    cudaFuncSetAttribute(tc_gemm<0,0>, cudaFuncAttributeMaxDynamicSharedMemorySize, SMEM_TOTAL);
    cudaFuncSetAttribute(tc_gemm<0,2>, cudaFuncAttributeMaxDynamicSharedMemorySize, SMEM_TOTAL);
    cudaFuncSetAttribute(tc_gemm<1,0>, cudaFuncAttributeMaxDynamicSharedMemorySize, SMEM_TOTAL);
    cudaFuncSetAttribute(tc_gemm<1,1>, cudaFuncAttributeMaxDynamicSharedMemorySize, SMEM_TOTAL);

    // ---- compaction + conversions
    mask_scan_kernel<<<BATCH, 256>>>(mask);
    gather_split_H<<<dim3(LSEQ, BATCH), 256>>>(H);
    gather_transpose_split<<<dim3(DH / 32, LSEQ / 32, BATCH), 256>>>(H);
    {
        int n4;
        n4 = (BATCH * TSEQ * DG) / 4;
        split_kernel<<<(n4 + 255) / 256, 256>>>((const float4*)G, (__nv_bfloat162*)pGhi,
                                                (__nv_bfloat162*)pGlo, n4);
        n4 = (DP * DH) / 4;
        split_kernel<<<(n4 + 255) / 256, 256>>>((const float4*)Wk, (__nv_bfloat162*)pWkhi,
                                                (__nv_bfloat162*)pWklo, n4);
        n4 = (DP * DG) / 4;
        split_kernel<<<(n4 + 255) / 256, 256>>>((const float4*)Wq, (__nv_bfloat162*)pWqhi,
                                                (__nv_bfloat162*)pWqlo, n4);
    }

    // 1) Kc = Hc * Wk^T  (per batch, m-exit at LcPad)
    tc_gemm<1,1><<<dim3(DP / 128, LSEQ / 128, BATCH), 256, SMEM_TOTAL>>>(
        pHhi, pHlo, pWkhi, pWklo, nullptr, pKhi, pKlo,
        DH, pLcPad, DH, DH, DP,
        (size_t)LSEQ * DH, 0, (size_t)LSEQ * DP, 1.0f);

    // 2) Q = G * Wq^T  (batch-flattened)
    tc_gemm<1,0><<<dim3(DP / 128, (BATCH * TSEQ) / 128, 1), 256, SMEM_TOTAL>>>(
        pGhi, pGlo, pWqhi, pWqlo, nullptr, pQhi, pQlo,
        DG, nullptr, DG, DG, DP, 0, 0, 0, 1.0f);

    // 3) S = (Q Kc^T)/16  (per batch, n-exit at LcPad)
    tc_gemm<0,2><<<dim3(LSEQ / 128, TSEQ / 128, BATCH), 256, SMEM_TOTAL>>>(
        pQhi, pQlo, pKhi, pKlo, pS, nullptr, nullptr,
        DP, pLcPad, DP, DP, LSEQ,
        (size_t)TSEQ * DP, (size_t)LSEQ * DP, (size_t)TSEQ * LSEQ, 0.0625f);

    // 4) alpha = softmax(S[0:Lc]) -> split bf16, zero pad to LcPad
    softmax_kernel<<<BATCH * TSEQ, 256>>>(pS, pShi, pSlo);

    // 5) Z = alpha * Hc  (per batch, K = LcPad dynamic)
    tc_gemm<0,0><<<dim3(DH / 128, TSEQ / 128, BATCH), 256, SMEM_TOTAL>>>(
        pShi, pSlo, pHThi, pHTlo, Z, nullptr, nullptr,
        0, pLcPad, LSEQ, LSEQ, DH,
        (size_t)TSEQ * LSEQ, (size_t)DH * LSEQ, (size_t)TSEQ * DH, 1.0f);
}